// round 9
// baseline (speedup 1.0000x reference)
#include <cuda_runtime.h>
#include <cuda_fp16.h>
#include <cstdint>

// Problem constants
#define Bz   16
#define Ss   1024
#define Ls   512
#define Dd   1024
#define Hh   8
#define DHd  128
#define WDd  256
#define BLn  (Bz*Ls)      // 8192
#define BSn  (Bz*Ss)      // 16384
#define KFn  (Dd+WDd)     // 1280
#define T1c  (BLn*Dd)             // 8388608
#define T2c  (Bz*(Ls+1)*Dd)       // 8404992

// Scratch (static device globals — allocation-free per harness rules)
__device__ __align__(128) __half g_ENCh[BSn*Dd];
__device__ __align__(128) __half g_SEMh[BLn*Dd];
__device__ __align__(128) __half g_WQh [Dd*Dd];
__device__ __align__(128) __half g_WKh [Dd*Dd];
__device__ __align__(128) __half g_WVh [Dd*Dd];
__device__ __align__(128) __half g_WOh [Dd*Dd];
__device__ __align__(128) __half g_WPh [Dd*KFn];
__device__ __align__(128) __half g_Qh  [BLn*Dd];
__device__ __align__(128) __half g_Kh  [BSn*Dd];
__device__ __align__(128) __half g_Vh  [BSn*Dd];
__device__ __align__(128) __half g_CTXh[BLn*Dd];
__device__ __align__(128) __half g_CATh[BLn*KFn];
__device__ __align__(128) float  g_EMB [BLn*Dd];
__device__ int g_is64;

// ---------------------------------------------------------------------------
__device__ __forceinline__ uint32_t smem_u32(const void* p) {
    uint32_t a;
    asm("{ .reg .u64 t; cvta.to.shared.u64 t, %1; cvt.u32.u64 %0, t; }" : "=r"(a) : "l"(p));
    return a;
}

__device__ __forceinline__ void cp16(uint32_t dst, const void* src) {
    asm volatile("cp.async.cg.shared.global [%0], [%1], 16;" :: "r"(dst), "l"(src));
}
#define CP_COMMIT() asm volatile("cp.async.commit_group;" ::: "memory")
#define CP_WAIT(n)  asm volatile("cp.async.wait_group %0;" :: "n"(n) : "memory")

#define LDSM4(r, addr) \
    asm volatile("ldmatrix.sync.aligned.m8n8.x4.shared.b16 {%0,%1,%2,%3}, [%4];" \
        : "=r"((r)[0]), "=r"((r)[1]), "=r"((r)[2]), "=r"((r)[3]) : "r"(addr))

#define MMA16816(c, a, b0, b1) \
    asm volatile("mma.sync.aligned.m16n8k16.row.col.f32.f16.f16.f32 " \
        "{%0,%1,%2,%3}, {%4,%5,%6,%7}, {%8,%9}, {%0,%1,%2,%3};" \
        : "+f"((c)[0]), "+f"((c)[1]), "+f"((c)[2]), "+f"((c)[3]) \
        : "r"((a)[0]), "r"((a)[1]), "r"((a)[2]), "r"((a)[3]), "r"(b0), "r"(b1))

// CTA tile 128x256: per-stage A 16KB + B 32KB
#define STG_B 49152
#define SM_TOT (3*STG_B)    // 147456

// ---------------------------------------------------------------------------
// GEMM core (NT): acc += A[bm:bm+128, :K] * W[bn:bn+256, :K]^T
// CTA tile 128x256, 512 threads, 16 warps of 32x64 (4x4), BK=64 halves,
// 3-stage cp.async pipeline. Crossbar traffic per MAC reduced vs 128x128.
__device__ __forceinline__ void gemm_tile_core(
    float acc[2][8][4],
    const __half* __restrict__ Ab, int lda,
    const __half* __restrict__ Wb, int ldw,
    int KT, uint32_t sb, int tid)
{
    const int warp = tid >> 5, lane = tid & 31;
    const int wm = warp & 3, wn = warp >> 2;

    auto load = [&](int stage, int kt) {
        const __half* Ap = Ab + kt * 64;
        const __half* Wp = Wb + kt * 64;
        uint32_t sa = sb + stage * STG_B;
        uint32_t sw = sa + 16384;
        #pragma unroll
        for (int i = 0; i < 2; i++) {          // A: 1024 chunks / 512 thr
            int c = tid + i * 512;
            int row = c >> 3, ch = c & 7;
            uint32_t off = (row << 7) + ((ch << 4) ^ ((row & 7) << 4));
            cp16(sa + off, Ap + (size_t)row * lda + ch * 8);
        }
        #pragma unroll
        for (int i = 0; i < 4; i++) {          // B: 2048 chunks / 512 thr
            int c = tid + i * 512;
            int row = c >> 3, ch = c & 7;
            uint32_t off = (row << 7) + ((ch << 4) ^ ((row & 7) << 4));
            cp16(sw + off, Wp + (size_t)row * ldw + ch * 8);
        }
        CP_COMMIT();
    };

    load(0, 0);
    load(1, 1);

    const int rlA = (lane & 7) + ((lane >> 3) & 1) * 8;
    const int caA = ((lane >> 4) & 1) << 4;
    const int rlB = (lane & 7) + ((lane >> 4) & 1) * 8;
    const int caB = ((lane >> 3) & 1) << 4;

    for (int kt = 0; kt < KT; kt++) {
        if (kt + 2 < KT) { CP_WAIT(1); } else { CP_WAIT(0); }
        __syncthreads();
        if (kt + 2 < KT) load((kt + 2) % 3, kt + 2);

        uint32_t ab = sb + (kt % 3) * STG_B;
        uint32_t bb = ab + 16384;

        #pragma unroll
        for (int q = 0; q < 4; q++) {
            uint32_t a[2][4], b[4][4];
            #pragma unroll
            for (int mt = 0; mt < 2; mt++) {
                int row = wm * 32 + mt * 16 + rlA;
                uint32_t addr = ab + (row << 7) + (((q << 5) + caA) ^ ((rlA & 7) << 4));
                LDSM4(a[mt], addr);
            }
            #pragma unroll
            for (int np = 0; np < 4; np++) {
                int row = wn * 64 + np * 16 + rlB;
                uint32_t addr = bb + (row << 7) + (((q << 5) + caB) ^ ((rlB & 7) << 4));
                LDSM4(b[np], addr);
            }
            #pragma unroll
            for (int mt = 0; mt < 2; mt++)
                #pragma unroll
                for (int np = 0; np < 4; np++) {
                    MMA16816(acc[mt][2*np],     a[mt], b[np][0], b[np][1]);
                    MMA16816(acc[mt][2*np + 1], a[mt], b[np][2], b[np][3]);
                }
        }
    }
}

// fp16 epilogue
__device__ __forceinline__ void epi_half(
    float acc[2][8][4], const float* __restrict__ bias, float alpha,
    __half* __restrict__ C, int ldc, int bm, int bn, int tid)
{
    const int warp = tid >> 5, lane = tid & 31;
    const int wm = warp & 3, wn = warp >> 2;
    const int g = lane >> 2, t2 = (lane & 3) * 2;
    #pragma unroll
    for (int nt = 0; nt < 8; nt++) {
        int c0 = bn + wn * 64 + nt * 8 + t2;
        float2 bv = *(const float2*)(bias + c0);
        #pragma unroll
        for (int mt = 0; mt < 2; mt++) {
            int r0 = bm + wm * 32 + mt * 16 + g;
            *(__half2*)(C + (size_t)r0 * ldc + c0) =
                __floats2half2_rn(alpha * (acc[mt][nt][0] + bv.x),
                                  alpha * (acc[mt][nt][1] + bv.y));
            *(__half2*)(C + (size_t)(r0 + 8) * ldc + c0) =
                __floats2half2_rn(alpha * (acc[mt][nt][2] + bv.x),
                                  alpha * (acc[mt][nt][3] + bv.y));
        }
    }
}

// ---------------------------------------------------------------------------
// fused Q + K + V projections, 1D grid of 256+512+512 blocks (tiles 128x256)
__global__ __launch_bounds__(512, 1) void qkv_gemm(
    const float* __restrict__ bq, const float* __restrict__ bk,
    const float* __restrict__ bv, float qscale)
{
    extern __shared__ char smem[];
    const uint32_t sb = smem_u32(smem);
    const int tid = threadIdx.x;
    int id = blockIdx.x;

    const __half* A; const __half* W; const float* bias; __half* C;
    float alpha; int bm, bn;
    if (id < 256) {
        A = g_SEMh; W = g_WQh; bias = bq; C = g_Qh; alpha = qscale;
        bm = (id >> 2) * 128; bn = (id & 3) * 256;
    } else if (id < 768) {
        int t = id - 256;
        A = g_ENCh; W = g_WKh; bias = bk; C = g_Kh; alpha = 1.0f;
        bm = (t >> 2) * 128; bn = (t & 3) * 256;
    } else {
        int t = id - 768;
        A = g_ENCh; W = g_WVh; bias = bv; C = g_Vh; alpha = 1.0f;
        bm = (t >> 2) * 128; bn = (t & 3) * 256;
    }

    float acc[2][8][4];
    #pragma unroll
    for (int i = 0; i < 2; i++)
        #pragma unroll
        for (int j = 0; j < 8; j++)
            #pragma unroll
            for (int r = 0; r < 4; r++) acc[i][j][r] = 0.f;

    gemm_tile_core(acc, A + (size_t)bm * Dd, Dd, W + (size_t)bn * Dd, Dd, 16, sb, tid);
    epi_half(acc, bias, alpha, C, Dd, bm, bn, tid);
}

// O projection: CTXh @ WOh^T + bo -> CATh (fp16, ldc = KFn)
__global__ __launch_bounds__(512, 1) void o_gemm(const float* __restrict__ bo) {
    extern __shared__ char smem[];
    const uint32_t sb = smem_u32(smem);
    const int tid = threadIdx.x;
    int id = blockIdx.x;
    int bm = (id >> 2) * 128, bn = (id & 3) * 256;

    float acc[2][8][4];
    #pragma unroll
    for (int i = 0; i < 2; i++)
        #pragma unroll
        for (int j = 0; j < 8; j++)
            #pragma unroll
            for (int r = 0; r < 4; r++) acc[i][j][r] = 0.f;

    gemm_tile_core(acc, g_CTXh + (size_t)bm * Dd, Dd, g_WOh + (size_t)bn * Dd, Dd, 16, sb, tid);
    epi_half(acc, bo, 1.0f, g_CATh, KFn, bm, bn, tid);
}

// final projection: CATh @ WPh^T + b_proj; direct dual store to d_out or fp32 EMB
__global__ __launch_bounds__(512, 1) void p_gemm(const float* __restrict__ bp,
                                                 float* __restrict__ out, int direct) {
    extern __shared__ char smem[];
    const uint32_t sb = smem_u32(smem);
    const int tid = threadIdx.x;
    int id = blockIdx.x;
    int bm = (id >> 2) * 128, bn = (id & 3) * 256;

    float acc[2][8][4];
    #pragma unroll
    for (int i = 0; i < 2; i++)
        #pragma unroll
        for (int j = 0; j < 8; j++)
            #pragma unroll
            for (int r = 0; r < 4; r++) acc[i][j][r] = 0.f;

    gemm_tile_core(acc, g_CATh + (size_t)bm * KFn, KFn, g_WPh + (size_t)bn * KFn, KFn, 20, sb, tid);

    const int warp = tid >> 5, lane = tid & 31;
    const int wm = warp & 3, wn = warp >> 2;
    const int g = lane >> 2, t2 = (lane & 3) * 2;
    #pragma unroll
    for (int nt = 0; nt < 8; nt++) {
        int c0 = bn + wn * 64 + nt * 8 + t2;
        float2 bv = *(const float2*)(bp + c0);
        #pragma unroll
        for (int mt = 0; mt < 2; mt++) {
            int r0 = bm + wm * 32 + mt * 16 + g;
            float2 o0 = {acc[mt][nt][0] + bv.x, acc[mt][nt][1] + bv.y};
            float2 o1 = {acc[mt][nt][2] + bv.x, acc[mt][nt][3] + bv.y};
            if (direct) {
                int b0 = r0 >> 9, l0 = r0 & 511;
                int rb = r0 + 8;
                int b1 = rb >> 9, l1 = rb & 511;
                *(float2*)(out + (size_t)r0 * Dd + c0) = o0;
                *(float2*)(out + (size_t)rb * Dd + c0) = o1;
                *(float2*)(out + T1c + ((size_t)b0 * (Ls+1) + l0 + 1) * Dd + c0) = o0;
                *(float2*)(out + T1c + ((size_t)b1 * (Ls+1) + l1 + 1) * Dd + c0) = o1;
            } else {
                *(float2*)(g_EMB + (size_t)r0 * Dd + c0)       = o0;
                *(float2*)(g_EMB + (size_t)(r0 + 8) * Dd + c0) = o1;
            }
        }
    }
}

// ---------------------------------------------------------------------------
__global__ void detect_kernel(const void* p) {
    __shared__ int nz;
    if (threadIdx.x == 0) nz = 0;
    __syncthreads();
    const int* q = (const int*)p;
    int bad = 0;
    for (int i = threadIdx.x * 2 + 1; i < 8192; i += 2 * blockDim.x)
        if (q[i] != 0) bad = 1;
    if (bad) atomicAdd(&nz, 1);
    __syncthreads();
    if (threadIdx.x == 0) g_is64 = (nz == 0) ? 1 : 0;
}

__device__ __forceinline__ int load_idx(const void* p, int i) {
    return g_is64 ? (int)((const long long*)p)[i] : ((const int*)p)[i];
}

// single-launch fp32 -> fp16 conversion of all 6 tensors (segment = blockIdx.y)
__global__ void f2h_all(const float* __restrict__ e, const float* __restrict__ q,
                        const float* __restrict__ k, const float* __restrict__ v,
                        const float* __restrict__ o, const float* __restrict__ p) {
    const float* srcs[6] = {e, q, k, v, o, p};
    __half* dsts[6] = {g_ENCh, g_WQh, g_WKh, g_WVh, g_WOh, g_WPh};
    const int n8s[6] = {BSn*Dd/8, Dd*Dd/8, Dd*Dd/8, Dd*Dd/8, Dd*Dd/8, Dd*KFn/8};
    int seg = blockIdx.y;
    const float* src = srcs[seg];
    __half* dst = dsts[seg];
    int n8 = n8s[seg];
    for (int i = blockIdx.x * blockDim.x + threadIdx.x; i < n8;
         i += gridDim.x * blockDim.x) {
        float4 a = ((const float4*)src)[2*i];
        float4 b = ((const float4*)src)[2*i+1];
        __half2 h[4];
        h[0] = __floats2half2_rn(a.x, a.y);
        h[1] = __floats2half2_rn(a.z, a.w);
        h[2] = __floats2half2_rn(b.x, b.y);
        h[3] = __floats2half2_rn(b.z, b.w);
        ((float4*)dst)[i] = *(float4*)h;
    }
}

// gather semantic rows from fp16 encoder copy
__global__ void gather_sem(const void* __restrict__ to_sem) {
    int m = blockIdx.x;
    int b = m >> 9;
    int idx = load_idx(to_sem, m);
    ((uint2*)(g_SEMh + (size_t)m * Dd))[threadIdx.x] =
        ((const uint2*)(g_ENCh + (size_t)(b * Ss + idx) * Dd))[threadIdx.x];
}

// type embedding into CAT tail; blocks >= 2048 write the root rows of d_out
__global__ void gather_type(const float* __restrict__ temb, const void* __restrict__ tt,
                            const float* __restrict__ root, float* __restrict__ out,
                            int direct) {
    if (blockIdx.x >= 2048) {
        if (direct) {
            int b = blockIdx.x - 2048;
            ((float4*)(out + (size_t)T1c + (size_t)b * (Ls + 1) * Dd))[threadIdx.x] =
                ((const float4*)root)[threadIdx.x];
        }
        return;
    }
    int m = blockIdx.x * 4 + (threadIdx.x >> 6);
    int l = threadIdx.x & 63;
    int t = load_idx(tt, m);
    float4 v = ((const float4*)(temb + (size_t)t * WDd))[l];
    __half2 h0 = __floats2half2_rn(v.x, v.y);
    __half2 h1 = __floats2half2_rn(v.z, v.w);
    uint2 u = { *(uint32_t*)&h0, *(uint32_t*)&h1 };
    ((uint2*)(g_CATh + (size_t)m * KFn + Dd))[l] = u;
}

// ---------------------------------------------------------------------------
// Sparse masked attention over fp16 Q/K/V; low-sync ordered compaction.
__global__ __launch_bounds__(128) void attn_kernel(
    const void* __restrict__ to_sem, const void* __restrict__ sem_syn)
{
    int bl = blockIdx.x;
    int b = bl >> 9, i = bl & 511;
    int tid = threadIdx.x;

    __shared__ int   s_idx[1032];
    __shared__ float s_sc[Hh][1032];
    __shared__ int   s_total;
    __shared__ int   s_wtot[4];
    __shared__ int   s_wbase[4];

    const int is64 = g_is64;
    const long long target = (long long)(i + 1);
    const long long* ss64 = (const long long*)sem_syn;
    const int*       ss32 = (const int*)sem_syn;
    const int base = b * Ss;

    int lane = tid & 31, w = tid >> 5;

    int loc[8];
    int cnt = 0;
    #pragma unroll
    for (int r = 0; r < 8; r++) {
        int j = tid * 8 + r;
        long long v = is64 ? ss64[base + j] : (long long)ss32[base + j];
        if (v == target) loc[cnt++] = j;
    }
    int inc = cnt;
    #pragma unroll
    for (int off = 1; off < 32; off <<= 1) {
        int n = __shfl_up_sync(0xffffffffu, inc, off);
        if (lane >= off) inc += n;
    }
    if (lane == 31) s_wtot[w] = inc;
    __syncthreads();
    if (tid == 0) {
        int s = 0;
        #pragma unroll
        for (int ww = 0; ww < 4; ww++) { int t2 = s_wtot[ww]; s_wbase[ww] = s; s += t2; }
        s_total = s;
    }
    __syncthreads();
    int basew = s_wbase[w] + inc - cnt;
    for (int c = 0; c < cnt; c++) s_idx[basew + c] = loc[c];

    int jself = load_idx(to_sem, bl);
    __syncthreads();
    if (tid == 0) {
        long long vs = is64 ? ss64[base + jself] : (long long)ss32[base + jself];
        if (vs != target) { s_idx[s_total] = jself; s_total = s_total + 1; }
    }
    __syncthreads();
    const int M = s_total;

    int h = tid >> 4, l16 = tid & 15;
    float qr[8];
    {
        uint4 u = *(const uint4*)(g_Qh + (size_t)bl * Dd + h * DHd + l16 * 8);
        const __half2* hp = (const __half2*)&u;
        float2 f0 = __half22float2(hp[0]), f1 = __half22float2(hp[1]);
        float2 f2 = __half22float2(hp[2]), f3 = __half22float2(hp[3]);
        qr[0]=f0.x; qr[1]=f0.y; qr[2]=f1.x; qr[3]=f1.y;
        qr[4]=f2.x; qr[5]=f2.y; qr[6]=f3.x; qr[7]=f3.y;
    }

    for (int m = 0; m < M; m++) {
        int j = s_idx[m];
        uint4 u = *(const uint4*)(g_Kh + (size_t)(base + j) * Dd + h * DHd + l16 * 8);
        const __half2* hp = (const __half2*)&u;
        float2 k0 = __half22float2(hp[0]), k1 = __half22float2(hp[1]);
        float2 k2 = __half22float2(hp[2]), k3 = __half22float2(hp[3]);
        float p = qr[0]*k0.x + qr[1]*k0.y + qr[2]*k1.x + qr[3]*k1.y
                + qr[4]*k2.x + qr[5]*k2.y + qr[6]*k3.x + qr[7]*k3.y;
        p += __shfl_xor_sync(0xffffffffu, p, 1);
        p += __shfl_xor_sync(0xffffffffu, p, 2);
        p += __shfl_xor_sync(0xffffffffu, p, 4);
        p += __shfl_xor_sync(0xffffffffu, p, 8);
        if (l16 == 0) s_sc[h][m] = p;
    }
    __syncthreads();

    float mx = -3.0e38f;
    for (int m = 0; m < M; m++) mx = fmaxf(mx, s_sc[h][m]);
    float den = 0.f;
    for (int m = 0; m < M; m++) den += expf(s_sc[h][m] - mx);

    float acc[8];
    #pragma unroll
    for (int c = 0; c < 8; c++) acc[c] = 0.f;
    for (int m = 0; m < M; m++) {
        float p = expf(s_sc[h][m] - mx);
        int j = s_idx[m];
        uint4 u = *(const uint4*)(g_Vh + (size_t)(base + j) * Dd + h * DHd + l16 * 8);
        const __half2* hp = (const __half2*)&u;
        float2 v0 = __half22float2(hp[0]), v1 = __half22float2(hp[1]);
        float2 v2 = __half22float2(hp[2]), v3 = __half22float2(hp[3]);
        acc[0] += p * v0.x; acc[1] += p * v0.y; acc[2] += p * v1.x; acc[3] += p * v1.y;
        acc[4] += p * v2.x; acc[5] += p * v2.y; acc[6] += p * v3.x; acc[7] += p * v3.y;
    }
    float inv = 1.0f / den;
    __half2 h0 = __floats2half2_rn(acc[0]*inv, acc[1]*inv);
    __half2 h1 = __floats2half2_rn(acc[2]*inv, acc[3]*inv);
    __half2 h2 = __floats2half2_rn(acc[4]*inv, acc[5]*inv);
    __half2 h3 = __floats2half2_rn(acc[6]*inv, acc[7]*inv);
    uint4 u = { *(uint32_t*)&h0, *(uint32_t*)&h1, *(uint32_t*)&h2, *(uint32_t*)&h3 };
    *(uint4*)(g_CTXh + (size_t)bl * Dd + h * DHd + l16 * 8) = u;
}

// ---------------------------------------------------------------------------
// fallback output packer (only used when out_size doesn't match full tuple)
__global__ void write_out(const float* __restrict__ root, float* __restrict__ out,
                          int out_size) {
    const int T1 = T1c, T2 = T2c;
    int base2, n;
    if (out_size >= T1 + T2)      { base2 = T1; n = T1 + T2; }
    else if (out_size == T2)      { base2 = 0;  n = T2; }
    else                          { base2 = -1; n = T1; }
    int n4 = n >> 2;
    for (int i4 = blockIdx.x * blockDim.x + threadIdx.x; i4 < n4;
         i4 += gridDim.x * blockDim.x) {
        int e = i4 << 2;
        float4 val;
        if (base2 >= 0 && e >= base2) {
            int off = e - base2;
            int b = off / ((Ls + 1) * Dd);
            int r = off - b * ((Ls + 1) * Dd);
            int l = r >> 10;
            int dd = r & (Dd - 1);
            if (l == 0)
                val = ((const float4*)root)[dd >> 2];
            else
                val = ((const float4*)(g_EMB + ((size_t)(b * Ls + l - 1) << 10)))[dd >> 2];
        } else {
            val = ((const float4*)g_EMB)[i4];
        }
        ((float4*)out)[i4] = val;
    }
}

// ---------------------------------------------------------------------------
extern "C" void kernel_launch(void* const* d_in, const int* in_sizes, int n_in,
                              void* d_out, int out_size) {
    const float* enc     = (const float*)d_in[0];
    const void*  to_sem  = d_in[1];
    const void*  tt      = d_in[2];
    const void*  sem_syn = d_in[3];
    const float* bq = (const float*)d_in[5];
    const float* bk = (const float*)d_in[7];
    const float* bv = (const float*)d_in[9];
    const float* bo = (const float*)d_in[11];
    const float* type_emb = (const float*)d_in[12];
    const float* b_proj   = (const float*)d_in[14];
    const float* root     = (const float*)d_in[15];

    cudaFuncSetAttribute(qkv_gemm, cudaFuncAttributeMaxDynamicSharedMemorySize, SM_TOT);
    cudaFuncSetAttribute(o_gemm,   cudaFuncAttributeMaxDynamicSharedMemorySize, SM_TOT);
    cudaFuncSetAttribute(p_gemm,   cudaFuncAttributeMaxDynamicSharedMemorySize, SM_TOT);

    const float qscale = 0.08838834764831843f;   // 1/sqrt(128)
    const int direct = (out_size >= T1c + T2c);

    detect_kernel<<<1, 512>>>(to_sem);
    f2h_all<<<dim3(256, 6), 256>>>(enc, (const float*)d_in[4], (const float*)d_in[6],
                                   (const float*)d_in[8], (const float*)d_in[10],
                                   (const float*)d_in[13]);
    gather_sem<<<BLn, 256>>>(to_sem);

    qkv_gemm<<<1280, 512, SM_TOT>>>(bq, bk, bv, qscale);

    attn_kernel<<<BLn, 128>>>(to_sem, sem_syn);

    o_gemm<<<256, 512, SM_TOT>>>(bo);
    gather_type<<<2048 + Bz, 256>>>(type_emb, tt, root, (float*)d_out, direct);

    p_gemm<<<256, 512, SM_TOT>>>(b_proj, (float*)d_out, direct);

    if (!direct) write_out<<<2048, 256>>>(root, (float*)d_out, out_size);
}

// round 10
// speedup vs baseline: 1.0583x; 1.0583x over previous
#include <cuda_runtime.h>
#include <cuda_fp16.h>
#include <cstdint>

// Problem constants
#define Bz   16
#define Ss   1024
#define Ls   512
#define Dd   1024
#define Hh   8
#define DHd  128
#define WDd  256
#define BLn  (Bz*Ls)      // 8192
#define BSn  (Bz*Ss)      // 16384
#define KFn  (Dd+WDd)     // 1280
#define T1c  (BLn*Dd)             // 8388608
#define T2c  (Bz*(Ls+1)*Dd)       // 8404992

// Scratch (static device globals — allocation-free per harness rules)
__device__ __align__(128) __half g_ENCh[BSn*Dd];
__device__ __align__(128) __half g_SEMh[BLn*Dd];
__device__ __align__(128) __half g_WQh [Dd*Dd];
__device__ __align__(128) __half g_WKh [Dd*Dd];
__device__ __align__(128) __half g_WVh [Dd*Dd];
__device__ __align__(128) __half g_WOh [Dd*Dd];
__device__ __align__(128) __half g_WPh [Dd*KFn];
__device__ __align__(128) __half g_Qh  [BLn*Dd];
__device__ __align__(128) __half g_Kh  [BSn*Dd];
__device__ __align__(128) __half g_Vh  [BSn*Dd];
__device__ __align__(128) __half g_CTXh[BLn*Dd];
__device__ __align__(128) __half g_CATh[BLn*KFn];
__device__ __align__(128) float  g_EMB [BLn*Dd];
__device__ int g_is64;

// ---------------------------------------------------------------------------
__device__ __forceinline__ uint32_t smem_u32(const void* p) {
    uint32_t a;
    asm("{ .reg .u64 t; cvta.to.shared.u64 t, %1; cvt.u32.u64 %0, t; }" : "=r"(a) : "l"(p));
    return a;
}

__device__ __forceinline__ void cp16(uint32_t dst, const void* src) {
    asm volatile("cp.async.cg.shared.global [%0], [%1], 16;" :: "r"(dst), "l"(src));
}
#define CP_COMMIT() asm volatile("cp.async.commit_group;" ::: "memory")
#define CP_WAIT(n)  asm volatile("cp.async.wait_group %0;" :: "n"(n) : "memory")

#define LDSM4(r, addr) \
    asm volatile("ldmatrix.sync.aligned.m8n8.x4.shared.b16 {%0,%1,%2,%3}, [%4];" \
        : "=r"((r)[0]), "=r"((r)[1]), "=r"((r)[2]), "=r"((r)[3]) : "r"(addr))

#define MMA16816(c, a, b0, b1) \
    asm volatile("mma.sync.aligned.m16n8k16.row.col.f32.f16.f16.f32 " \
        "{%0,%1,%2,%3}, {%4,%5,%6,%7}, {%8,%9}, {%0,%1,%2,%3};" \
        : "+f"((c)[0]), "+f"((c)[1]), "+f"((c)[2]), "+f"((c)[3]) \
        : "r"((a)[0]), "r"((a)[1]), "r"((a)[2]), "r"((a)[3]), "r"(b0), "r"(b1))

#define STG_B 32768
#define SM_TOT (3*STG_B)

// ---------------------------------------------------------------------------
// GEMM core (NT): acc += A[bm:bm+128, :K] * W[bn:bn+128, :K]^T
// 128x128 CTA tile, 256 threads, 8 warps of 32x64 (4x2), BK=64 halves,
// 3-stage cp.async pipeline, single-buffered fragments (best-measured R7
// configuration), with hoisted per-thread ldmatrix row-base addresses.
__device__ __forceinline__ void gemm_tile_core(
    float acc[2][8][4],
    const __half* __restrict__ Ab, int lda,
    const __half* __restrict__ Wb, int ldw,
    int KT, uint32_t sb, int tid)
{
    const int warp = tid >> 5, lane = tid & 31;
    const int wm = warp & 3, wn = warp >> 2;

    auto load = [&](int stage, int kt) {
        const __half* Ap = Ab + kt * 64;
        const __half* Wp = Wb + kt * 64;
        uint32_t sa = sb + stage * STG_B;
        uint32_t sw = sa + 16384;
        #pragma unroll
        for (int i = 0; i < 4; i++) {
            int c = tid + i * 256;
            int row = c >> 3, ch = c & 7;
            uint32_t off = (row << 7) + ((ch << 4) ^ ((row & 7) << 4));
            cp16(sa + off, Ap + (size_t)row * lda + ch * 8);
            cp16(sw + off, Wp + (size_t)row * ldw + ch * 8);
        }
        CP_COMMIT();
    };

    load(0, 0);
    load(1, 1);

    const int rlA = (lane & 7) + ((lane >> 3) & 1) * 8;
    const int caA = ((lane >> 4) & 1) << 4;
    const int rlB = (lane & 7) + ((lane >> 4) & 1) * 8;
    const int caB = ((lane >> 3) & 1) << 4;
    const uint32_t swA = (uint32_t)(rlA & 7) << 4;
    const uint32_t swB = (uint32_t)(rlB & 7) << 4;
    // hoisted row-base byte offsets (constant per thread across all ktiles)
    const uint32_t rowA0 = (uint32_t)((wm * 32 +  0 + rlA) << 7);
    const uint32_t rowA1 = (uint32_t)((wm * 32 + 16 + rlA) << 7);
    const uint32_t rowB0 = (uint32_t)((wn * 64 +  0 + rlB) << 7);
    const uint32_t rowB1 = (uint32_t)((wn * 64 + 16 + rlB) << 7);
    const uint32_t rowB2 = (uint32_t)((wn * 64 + 32 + rlB) << 7);
    const uint32_t rowB3 = (uint32_t)((wn * 64 + 48 + rlB) << 7);

    for (int kt = 0; kt < KT; kt++) {
        if (kt + 2 < KT) { CP_WAIT(1); } else { CP_WAIT(0); }
        __syncthreads();
        if (kt + 2 < KT) load((kt + 2) % 3, kt + 2);

        uint32_t ab = sb + (kt % 3) * STG_B;
        uint32_t bb = ab + 16384;

        #pragma unroll
        for (int q = 0; q < 4; q++) {
            const uint32_t cA = (uint32_t)((q << 5) + caA) ^ swA;
            const uint32_t cB = (uint32_t)((q << 5) + caB) ^ swB;
            uint32_t a[2][4], b[4][4];
            LDSM4(a[0], ab + rowA0 + cA);
            LDSM4(a[1], ab + rowA1 + cA);
            LDSM4(b[0], bb + rowB0 + cB);
            LDSM4(b[1], bb + rowB1 + cB);
            LDSM4(b[2], bb + rowB2 + cB);
            LDSM4(b[3], bb + rowB3 + cB);
            #pragma unroll
            for (int mt = 0; mt < 2; mt++)
                #pragma unroll
                for (int np = 0; np < 4; np++) {
                    MMA16816(acc[mt][2*np],     a[mt], b[np][0], b[np][1]);
                    MMA16816(acc[mt][2*np + 1], a[mt], b[np][2], b[np][3]);
                }
        }
    }
}

// fp16 epilogue
__device__ __forceinline__ void epi_half(
    float acc[2][8][4], const float* __restrict__ bias, float alpha,
    __half* __restrict__ C, int ldc, int bm, int bn, int tid)
{
    const int warp = tid >> 5, lane = tid & 31;
    const int wm = warp & 3, wn = warp >> 2;
    const int g = lane >> 2, t2 = (lane & 3) * 2;
    #pragma unroll
    for (int nt = 0; nt < 8; nt++) {
        int c0 = bn + wn * 64 + nt * 8 + t2;
        float2 bv = *(const float2*)(bias + c0);
        #pragma unroll
        for (int mt = 0; mt < 2; mt++) {
            int r0 = bm + wm * 32 + mt * 16 + g;
            *(__half2*)(C + (size_t)r0 * ldc + c0) =
                __floats2half2_rn(alpha * (acc[mt][nt][0] + bv.x),
                                  alpha * (acc[mt][nt][1] + bv.y));
            *(__half2*)(C + (size_t)(r0 + 8) * ldc + c0) =
                __floats2half2_rn(alpha * (acc[mt][nt][2] + bv.x),
                                  alpha * (acc[mt][nt][3] + bv.y));
        }
    }
}

// ---------------------------------------------------------------------------
// fused Q + K + V projections, 1D grid of 512+1024+1024 blocks
__global__ __launch_bounds__(256, 2) void qkv_gemm(
    const float* __restrict__ bq, const float* __restrict__ bk,
    const float* __restrict__ bv, float qscale)
{
    extern __shared__ char smem[];
    const uint32_t sb = smem_u32(smem);
    const int tid = threadIdx.x;
    int id = blockIdx.x;

    const __half* A; const __half* W; const float* bias; __half* C;
    float alpha; int bm, bn;
    if (id < 512) {
        A = g_SEMh; W = g_WQh; bias = bq; C = g_Qh; alpha = qscale;
        bm = (id >> 3) * 128; bn = (id & 7) * 128;
    } else if (id < 1536) {
        int t = id - 512;
        A = g_ENCh; W = g_WKh; bias = bk; C = g_Kh; alpha = 1.0f;
        bm = (t >> 3) * 128; bn = (t & 7) * 128;
    } else {
        int t = id - 1536;
        A = g_ENCh; W = g_WVh; bias = bv; C = g_Vh; alpha = 1.0f;
        bm = (t >> 3) * 128; bn = (t & 7) * 128;
    }

    float acc[2][8][4];
    #pragma unroll
    for (int i = 0; i < 2; i++)
        #pragma unroll
        for (int j = 0; j < 8; j++)
            #pragma unroll
            for (int r = 0; r < 4; r++) acc[i][j][r] = 0.f;

    gemm_tile_core(acc, A + (size_t)bm * Dd, Dd, W + (size_t)bn * Dd, Dd, 16, sb, tid);
    epi_half(acc, bias, alpha, C, Dd, bm, bn, tid);
}

// O projection: CTXh @ WOh^T + bo -> CATh (fp16, ldc = KFn)
__global__ __launch_bounds__(256, 2) void o_gemm(const float* __restrict__ bo) {
    extern __shared__ char smem[];
    const uint32_t sb = smem_u32(smem);
    const int tid = threadIdx.x;
    int id = blockIdx.x;
    int bm = (id >> 3) * 128, bn = (id & 7) * 128;

    float acc[2][8][4];
    #pragma unroll
    for (int i = 0; i < 2; i++)
        #pragma unroll
        for (int j = 0; j < 8; j++)
            #pragma unroll
            for (int r = 0; r < 4; r++) acc[i][j][r] = 0.f;

    gemm_tile_core(acc, g_CTXh + (size_t)bm * Dd, Dd, g_WOh + (size_t)bn * Dd, Dd, 16, sb, tid);
    epi_half(acc, bo, 1.0f, g_CATh, KFn, bm, bn, tid);
}

// final projection: CATh @ WPh^T + b_proj; direct dual store to d_out or fp32 EMB
__global__ __launch_bounds__(256, 2) void p_gemm(const float* __restrict__ bp,
                                                 float* __restrict__ out, int direct) {
    extern __shared__ char smem[];
    const uint32_t sb = smem_u32(smem);
    const int tid = threadIdx.x;
    int id = blockIdx.x;
    int bm = (id >> 3) * 128, bn = (id & 7) * 128;

    float acc[2][8][4];
    #pragma unroll
    for (int i = 0; i < 2; i++)
        #pragma unroll
        for (int j = 0; j < 8; j++)
            #pragma unroll
            for (int r = 0; r < 4; r++) acc[i][j][r] = 0.f;

    gemm_tile_core(acc, g_CATh + (size_t)bm * KFn, KFn, g_WPh + (size_t)bn * KFn, KFn, 20, sb, tid);

    const int warp = tid >> 5, lane = tid & 31;
    const int wm = warp & 3, wn = warp >> 2;
    const int g = lane >> 2, t2 = (lane & 3) * 2;
    #pragma unroll
    for (int nt = 0; nt < 8; nt++) {
        int c0 = bn + wn * 64 + nt * 8 + t2;
        float2 bv = *(const float2*)(bp + c0);
        #pragma unroll
        for (int mt = 0; mt < 2; mt++) {
            int r0 = bm + wm * 32 + mt * 16 + g;
            float2 o0 = {acc[mt][nt][0] + bv.x, acc[mt][nt][1] + bv.y};
            float2 o1 = {acc[mt][nt][2] + bv.x, acc[mt][nt][3] + bv.y};
            if (direct) {
                int b0 = r0 >> 9, l0 = r0 & 511;
                int rb = r0 + 8;
                int b1 = rb >> 9, l1 = rb & 511;
                *(float2*)(out + (size_t)r0 * Dd + c0) = o0;
                *(float2*)(out + (size_t)rb * Dd + c0) = o1;
                *(float2*)(out + T1c + ((size_t)b0 * (Ls+1) + l0 + 1) * Dd + c0) = o0;
                *(float2*)(out + T1c + ((size_t)b1 * (Ls+1) + l1 + 1) * Dd + c0) = o1;
            } else {
                *(float2*)(g_EMB + (size_t)r0 * Dd + c0)       = o0;
                *(float2*)(g_EMB + (size_t)(r0 + 8) * Dd + c0) = o1;
            }
        }
    }
}

// ---------------------------------------------------------------------------
__device__ __forceinline__ int load_idx(const void* p, int i) {
    return g_is64 ? (int)((const long long*)p)[i] : ((const int*)p)[i];
}

// fp32 -> fp16 conversion of all 6 tensors + index-dtype detection (seg 6)
__global__ void f2h_all(const float* __restrict__ e, const float* __restrict__ q,
                        const float* __restrict__ k, const float* __restrict__ v,
                        const float* __restrict__ o, const float* __restrict__ p,
                        const void* __restrict__ to_sem) {
    int seg = blockIdx.y;
    if (seg == 6) {
        // index dtype detection: int64 => odd 32-bit words all zero
        __shared__ int nz;
        if (threadIdx.x == 0) nz = 0;
        __syncthreads();
        if (blockIdx.x == 0) {
            const int* qw = (const int*)to_sem;
            int bad = 0;
            for (int i = threadIdx.x * 2 + 1; i < 8192; i += 2 * blockDim.x)
                if (qw[i] != 0) bad = 1;
            if (bad) atomicAdd(&nz, 1);
            __syncthreads();
            if (threadIdx.x == 0) g_is64 = (nz == 0) ? 1 : 0;
        }
        return;
    }
    const float* srcs[6] = {e, q, k, v, o, p};
    __half* dsts[6] = {g_ENCh, g_WQh, g_WKh, g_WVh, g_WOh, g_WPh};
    const int n8s[6] = {BSn*Dd/8, Dd*Dd/8, Dd*Dd/8, Dd*Dd/8, Dd*Dd/8, Dd*KFn/8};
    const float* src = srcs[seg];
    __half* dst = dsts[seg];
    int n8 = n8s[seg];
    for (int i = blockIdx.x * blockDim.x + threadIdx.x; i < n8;
         i += gridDim.x * blockDim.x) {
        float4 a = ((const float4*)src)[2*i];
        float4 b = ((const float4*)src)[2*i+1];
        __half2 h[4];
        h[0] = __floats2half2_rn(a.x, a.y);
        h[1] = __floats2half2_rn(a.z, a.w);
        h[2] = __floats2half2_rn(b.x, b.y);
        h[3] = __floats2half2_rn(b.z, b.w);
        ((float4*)dst)[i] = *(float4*)h;
    }
}

// gather semantic rows from fp16 encoder copy
__global__ void gather_sem(const void* __restrict__ to_sem) {
    int m = blockIdx.x;
    int b = m >> 9;
    int idx = load_idx(to_sem, m);
    ((uint2*)(g_SEMh + (size_t)m * Dd))[threadIdx.x] =
        ((const uint2*)(g_ENCh + (size_t)(b * Ss + idx) * Dd))[threadIdx.x];
}

// type embedding into CAT tail; blocks >= 2048 write the root rows of d_out
__global__ void gather_type(const float* __restrict__ temb, const void* __restrict__ tt,
                            const float* __restrict__ root, float* __restrict__ out,
                            int direct) {
    if (blockIdx.x >= 2048) {
        if (direct) {
            int b = blockIdx.x - 2048;
            ((float4*)(out + (size_t)T1c + (size_t)b * (Ls + 1) * Dd))[threadIdx.x] =
                ((const float4*)root)[threadIdx.x];
        }
        return;
    }
    int m = blockIdx.x * 4 + (threadIdx.x >> 6);
    int l = threadIdx.x & 63;
    int t = load_idx(tt, m);
    float4 v = ((const float4*)(temb + (size_t)t * WDd))[l];
    __half2 h0 = __floats2half2_rn(v.x, v.y);
    __half2 h1 = __floats2half2_rn(v.z, v.w);
    uint2 u = { *(uint32_t*)&h0, *(uint32_t*)&h1 };
    ((uint2*)(g_CATh + (size_t)m * KFn + Dd))[l] = u;
}

// ---------------------------------------------------------------------------
// Sparse masked attention over fp16 Q/K/V; low-sync ordered compaction.
__global__ __launch_bounds__(128) void attn_kernel(
    const void* __restrict__ to_sem, const void* __restrict__ sem_syn)
{
    int bl = blockIdx.x;
    int b = bl >> 9, i = bl & 511;
    int tid = threadIdx.x;

    __shared__ int   s_idx[1032];
    __shared__ float s_sc[Hh][1032];
    __shared__ int   s_total;
    __shared__ int   s_wtot[4];
    __shared__ int   s_wbase[4];

    const int is64 = g_is64;
    const long long target = (long long)(i + 1);
    const long long* ss64 = (const long long*)sem_syn;
    const int*       ss32 = (const int*)sem_syn;
    const int base = b * Ss;

    int lane = tid & 31, w = tid >> 5;

    int loc[8];
    int cnt = 0;
    #pragma unroll
    for (int r = 0; r < 8; r++) {
        int j = tid * 8 + r;
        long long v = is64 ? ss64[base + j] : (long long)ss32[base + j];
        if (v == target) loc[cnt++] = j;
    }
    int inc = cnt;
    #pragma unroll
    for (int off = 1; off < 32; off <<= 1) {
        int n = __shfl_up_sync(0xffffffffu, inc, off);
        if (lane >= off) inc += n;
    }
    if (lane == 31) s_wtot[w] = inc;
    __syncthreads();
    if (tid == 0) {
        int s = 0;
        #pragma unroll
        for (int ww = 0; ww < 4; ww++) { int t2 = s_wtot[ww]; s_wbase[ww] = s; s += t2; }
        s_total = s;
    }
    __syncthreads();
    int basew = s_wbase[w] + inc - cnt;
    for (int c = 0; c < cnt; c++) s_idx[basew + c] = loc[c];

    int jself = load_idx(to_sem, bl);
    __syncthreads();
    if (tid == 0) {
        long long vs = is64 ? ss64[base + jself] : (long long)ss32[base + jself];
        if (vs != target) { s_idx[s_total] = jself; s_total = s_total + 1; }
    }
    __syncthreads();
    const int M = s_total;

    int h = tid >> 4, l16 = tid & 15;
    float qr[8];
    {
        uint4 u = *(const uint4*)(g_Qh + (size_t)bl * Dd + h * DHd + l16 * 8);
        const __half2* hp = (const __half2*)&u;
        float2 f0 = __half22float2(hp[0]), f1 = __half22float2(hp[1]);
        float2 f2 = __half22float2(hp[2]), f3 = __half22float2(hp[3]);
        qr[0]=f0.x; qr[1]=f0.y; qr[2]=f1.x; qr[3]=f1.y;
        qr[4]=f2.x; qr[5]=f2.y; qr[6]=f3.x; qr[7]=f3.y;
    }

    for (int m = 0; m < M; m++) {
        int j = s_idx[m];
        uint4 u = *(const uint4*)(g_Kh + (size_t)(base + j) * Dd + h * DHd + l16 * 8);
        const __half2* hp = (const __half2*)&u;
        float2 k0 = __half22float2(hp[0]), k1 = __half22float2(hp[1]);
        float2 k2 = __half22float2(hp[2]), k3 = __half22float2(hp[3]);
        float p = qr[0]*k0.x + qr[1]*k0.y + qr[2]*k1.x + qr[3]*k1.y
                + qr[4]*k2.x + qr[5]*k2.y + qr[6]*k3.x + qr[7]*k3.y;
        p += __shfl_xor_sync(0xffffffffu, p, 1);
        p += __shfl_xor_sync(0xffffffffu, p, 2);
        p += __shfl_xor_sync(0xffffffffu, p, 4);
        p += __shfl_xor_sync(0xffffffffu, p, 8);
        if (l16 == 0) s_sc[h][m] = p;
    }
    __syncthreads();

    float mx = -3.0e38f;
    for (int m = 0; m < M; m++) mx = fmaxf(mx, s_sc[h][m]);
    float den = 0.f;
    for (int m = 0; m < M; m++) den += expf(s_sc[h][m] - mx);

    float acc[8];
    #pragma unroll
    for (int c = 0; c < 8; c++) acc[c] = 0.f;
    for (int m = 0; m < M; m++) {
        float p = expf(s_sc[h][m] - mx);
        int j = s_idx[m];
        uint4 u = *(const uint4*)(g_Vh + (size_t)(base + j) * Dd + h * DHd + l16 * 8);
        const __half2* hp = (const __half2*)&u;
        float2 v0 = __half22float2(hp[0]), v1 = __half22float2(hp[1]);
        float2 v2 = __half22float2(hp[2]), v3 = __half22float2(hp[3]);
        acc[0] += p * v0.x; acc[1] += p * v0.y; acc[2] += p * v1.x; acc[3] += p * v1.y;
        acc[4] += p * v2.x; acc[5] += p * v2.y; acc[6] += p * v3.x; acc[7] += p * v3.y;
    }
    float inv = 1.0f / den;
    __half2 h0 = __floats2half2_rn(acc[0]*inv, acc[1]*inv);
    __half2 h1 = __floats2half2_rn(acc[2]*inv, acc[3]*inv);
    __half2 h2 = __floats2half2_rn(acc[4]*inv, acc[5]*inv);
    __half2 h3 = __floats2half2_rn(acc[6]*inv, acc[7]*inv);
    uint4 u = { *(uint32_t*)&h0, *(uint32_t*)&h1, *(uint32_t*)&h2, *(uint32_t*)&h3 };
    *(uint4*)(g_CTXh + (size_t)bl * Dd + h * DHd + l16 * 8) = u;
}

// ---------------------------------------------------------------------------
// fallback output packer (only used when out_size doesn't match full tuple)
__global__ void write_out(const float* __restrict__ root, float* __restrict__ out,
                          int out_size) {
    const int T1 = T1c, T2 = T2c;
    int base2, n;
    if (out_size >= T1 + T2)      { base2 = T1; n = T1 + T2; }
    else if (out_size == T2)      { base2 = 0;  n = T2; }
    else                          { base2 = -1; n = T1; }
    int n4 = n >> 2;
    for (int i4 = blockIdx.x * blockDim.x + threadIdx.x; i4 < n4;
         i4 += gridDim.x * blockDim.x) {
        int e = i4 << 2;
        float4 val;
        if (base2 >= 0 && e >= base2) {
            int off = e - base2;
            int b = off / ((Ls + 1) * Dd);
            int r = off - b * ((Ls + 1) * Dd);
            int l = r >> 10;
            int dd = r & (Dd - 1);
            if (l == 0)
                val = ((const float4*)root)[dd >> 2];
            else
                val = ((const float4*)(g_EMB + ((size_t)(b * Ls + l - 1) << 10)))[dd >> 2];
        } else {
            val = ((const float4*)g_EMB)[i4];
        }
        ((float4*)out)[i4] = val;
    }
}

// ---------------------------------------------------------------------------
extern "C" void kernel_launch(void* const* d_in, const int* in_sizes, int n_in,
                              void* d_out, int out_size) {
    const float* enc     = (const float*)d_in[0];
    const void*  to_sem  = d_in[1];
    const void*  tt      = d_in[2];
    const void*  sem_syn = d_in[3];
    const float* bq = (const float*)d_in[5];
    const float* bk = (const float*)d_in[7];
    const float* bv = (const float*)d_in[9];
    const float* bo = (const float*)d_in[11];
    const float* type_emb = (const float*)d_in[12];
    const float* b_proj   = (const float*)d_in[14];
    const float* root     = (const float*)d_in[15];

    cudaFuncSetAttribute(qkv_gemm, cudaFuncAttributeMaxDynamicSharedMemorySize, SM_TOT);
    cudaFuncSetAttribute(o_gemm,   cudaFuncAttributeMaxDynamicSharedMemorySize, SM_TOT);
    cudaFuncSetAttribute(p_gemm,   cudaFuncAttributeMaxDynamicSharedMemorySize, SM_TOT);

    const float qscale = 0.08838834764831843f;   // 1/sqrt(128)
    const int direct = (out_size >= T1c + T2c);

    // conversions + index-dtype detection in one launch
    f2h_all<<<dim3(256, 7), 256>>>(enc, (const float*)d_in[4], (const float*)d_in[6],
                                   (const float*)d_in[8], (const float*)d_in[10],
                                   (const float*)d_in[13], to_sem);
    gather_sem<<<BLn, 256>>>(to_sem);
    // type-embedding gather hoisted off the o_gemm -> p_gemm critical path
    gather_type<<<2048 + Bz, 256>>>(type_emb, tt, root, (float*)d_out, direct);

    qkv_gemm<<<2560, 256, SM_TOT>>>(bq, bk, bv, qscale);

    attn_kernel<<<BLn, 128>>>(to_sem, sem_syn);

    o_gemm<<<512, 256, SM_TOT>>>(bo);

    p_gemm<<<512, 256, SM_TOT>>>(b_proj, (float*)d_out, direct);

    if (!direct) write_out<<<2048, 256>>>(root, (float*)d_out, out_size);
}

// round 11
// speedup vs baseline: 1.1005x; 1.0399x over previous
#include <cuda_runtime.h>
#include <cuda_fp16.h>
#include <cstdint>

// Problem constants
#define Bz   16
#define Ss   1024
#define Ls   512
#define Dd   1024
#define Hh   8
#define DHd  128
#define WDd  256
#define BLn  (Bz*Ls)      // 8192
#define BSn  (Bz*Ss)      // 16384
#define KFn  (Dd+WDd)     // 1280
#define T1c  (BLn*Dd)             // 8388608
#define T2c  (Bz*(Ls+1)*Dd)       // 8404992
#define BKT  64           // bucket capacity per (b,i)

// Scratch (static device globals — allocation-free per harness rules)
__device__ __align__(128) __half g_ENCh[BSn*Dd];
__device__ __align__(128) __half g_WQh [Dd*Dd];
__device__ __align__(128) __half g_WKh [Dd*Dd];
__device__ __align__(128) __half g_WVh [Dd*Dd];
__device__ __align__(128) __half g_WOh [Dd*Dd];
__device__ __align__(128) __half g_WPh [Dd*KFn];
__device__ __align__(128) __half g_Qh  [BLn*Dd];
__device__ __align__(128) __half g_Kh  [BSn*Dd];
__device__ __align__(128) __half g_Vh  [BSn*Dd];
__device__ __align__(128) __half g_CTXh[BLn*Dd];
__device__ __align__(128) __half g_CATh[BLn*KFn];
__device__ __align__(128) float  g_EMB [BLn*Dd];
__device__ int            g_bcnt[BLn];
__device__ unsigned short g_bkt [BLn*BKT];
__device__ int g_is64;

// ---------------------------------------------------------------------------
__device__ __forceinline__ uint32_t smem_u32(const void* p) {
    uint32_t a;
    asm("{ .reg .u64 t; cvta.to.shared.u64 t, %1; cvt.u32.u64 %0, t; }" : "=r"(a) : "l"(p));
    return a;
}

__device__ __forceinline__ void cp16(uint32_t dst, const void* src) {
    asm volatile("cp.async.cg.shared.global [%0], [%1], 16;" :: "r"(dst), "l"(src));
}
#define CP_COMMIT() asm volatile("cp.async.commit_group;" ::: "memory")
#define CP_WAIT(n)  asm volatile("cp.async.wait_group %0;" :: "n"(n) : "memory")

#define LDSM4(r, addr) \
    asm volatile("ldmatrix.sync.aligned.m8n8.x4.shared.b16 {%0,%1,%2,%3}, [%4];" \
        : "=r"((r)[0]), "=r"((r)[1]), "=r"((r)[2]), "=r"((r)[3]) : "r"(addr))

#define MMA16816(c, a, b0, b1) \
    asm volatile("mma.sync.aligned.m16n8k16.row.col.f32.f16.f16.f32 " \
        "{%0,%1,%2,%3}, {%4,%5,%6,%7}, {%8,%9}, {%0,%1,%2,%3};" \
        : "+f"((c)[0]), "+f"((c)[1]), "+f"((c)[2]), "+f"((c)[3]) \
        : "r"((a)[0]), "r"((a)[1]), "r"((a)[2]), "r"((a)[3]), "r"(b0), "r"(b1))

#define STG_B 32768
#define SM_TOT (3*STG_B)

__device__ __forceinline__ int load_idx_i(const void* p, int i, int is64) {
    return is64 ? (int)((const long long*)p)[i] : ((const int*)p)[i];
}

// ---------------------------------------------------------------------------
// GEMM core (NT): acc += A[bm:bm+128, :K] * W[bn:bn+128, :K]^T
// 128x128 CTA tile, 256 threads, 8 warps of 32x64 (4x2), BK=64 halves,
// 3-stage cp.async pipeline (best-measured R7/R10 configuration).
// gmode=1: A rows gathered via to_sem (row m -> ENCh[b*1024 + to_sem[m]]).
__device__ __forceinline__ void gemm_tile_core(
    float acc[2][8][4],
    const __half* __restrict__ Ab, int lda,
    const __half* __restrict__ Wb, int ldw,
    int KT, uint32_t sb, int tid,
    int gmode, const void* __restrict__ ts, int gbm, int is64)
{
    const int warp = tid >> 5, lane = tid & 31;
    const int wm = warp & 3, wn = warp >> 2;

    auto load = [&](int stage, int kt) {
        const int k0 = kt * 64;
        uint32_t sa = sb + stage * STG_B;
        uint32_t sw = sa + 16384;
        #pragma unroll
        for (int i = 0; i < 4; i++) {
            int c = tid + i * 256;
            int row = c >> 3, ch = c & 7;
            uint32_t off = (row << 7) + ((ch << 4) ^ ((row & 7) << 4));
            const __half* ap;
            if (gmode) {
                int m = gbm + row;
                int idx = load_idx_i(ts, m, is64);
                ap = Ab + (((size_t)(m >> 9) << 10) + (size_t)idx) * Dd + k0;
            } else {
                ap = Ab + (size_t)row * lda + k0;
            }
            cp16(sa + off, ap + ch * 8);
            cp16(sw + off, Wb + (size_t)row * ldw + k0 + ch * 8);
        }
        CP_COMMIT();
    };

    load(0, 0);
    load(1, 1);

    const int rlA = (lane & 7) + ((lane >> 3) & 1) * 8;
    const int caA = ((lane >> 4) & 1) << 4;
    const int rlB = (lane & 7) + ((lane >> 4) & 1) * 8;
    const int caB = ((lane >> 3) & 1) << 4;
    const uint32_t swA = (uint32_t)(rlA & 7) << 4;
    const uint32_t swB = (uint32_t)(rlB & 7) << 4;
    const uint32_t rowA0 = (uint32_t)((wm * 32 +  0 + rlA) << 7);
    const uint32_t rowA1 = (uint32_t)((wm * 32 + 16 + rlA) << 7);
    const uint32_t rowB0 = (uint32_t)((wn * 64 +  0 + rlB) << 7);
    const uint32_t rowB1 = (uint32_t)((wn * 64 + 16 + rlB) << 7);
    const uint32_t rowB2 = (uint32_t)((wn * 64 + 32 + rlB) << 7);
    const uint32_t rowB3 = (uint32_t)((wn * 64 + 48 + rlB) << 7);

    for (int kt = 0; kt < KT; kt++) {
        if (kt + 2 < KT) { CP_WAIT(1); } else { CP_WAIT(0); }
        __syncthreads();
        if (kt + 2 < KT) load((kt + 2) % 3, kt + 2);

        uint32_t ab = sb + (kt % 3) * STG_B;
        uint32_t bb = ab + 16384;

        #pragma unroll
        for (int q = 0; q < 4; q++) {
            const uint32_t cA = (uint32_t)((q << 5) + caA) ^ swA;
            const uint32_t cB = (uint32_t)((q << 5) + caB) ^ swB;
            uint32_t a[2][4], b[4][4];
            LDSM4(a[0], ab + rowA0 + cA);
            LDSM4(a[1], ab + rowA1 + cA);
            LDSM4(b[0], bb + rowB0 + cB);
            LDSM4(b[1], bb + rowB1 + cB);
            LDSM4(b[2], bb + rowB2 + cB);
            LDSM4(b[3], bb + rowB3 + cB);
            #pragma unroll
            for (int mt = 0; mt < 2; mt++)
                #pragma unroll
                for (int np = 0; np < 4; np++) {
                    MMA16816(acc[mt][2*np],     a[mt], b[np][0], b[np][1]);
                    MMA16816(acc[mt][2*np + 1], a[mt], b[np][2], b[np][3]);
                }
        }
    }
}

// fp16 epilogue
__device__ __forceinline__ void epi_half(
    float acc[2][8][4], const float* __restrict__ bias, float alpha,
    __half* __restrict__ C, int ldc, int bm, int bn, int tid)
{
    const int warp = tid >> 5, lane = tid & 31;
    const int wm = warp & 3, wn = warp >> 2;
    const int g = lane >> 2, t2 = (lane & 3) * 2;
    #pragma unroll
    for (int nt = 0; nt < 8; nt++) {
        int c0 = bn + wn * 64 + nt * 8 + t2;
        float2 bv = *(const float2*)(bias + c0);
        #pragma unroll
        for (int mt = 0; mt < 2; mt++) {
            int r0 = bm + wm * 32 + mt * 16 + g;
            *(__half2*)(C + (size_t)r0 * ldc + c0) =
                __floats2half2_rn(alpha * (acc[mt][nt][0] + bv.x),
                                  alpha * (acc[mt][nt][1] + bv.y));
            *(__half2*)(C + (size_t)(r0 + 8) * ldc + c0) =
                __floats2half2_rn(alpha * (acc[mt][nt][2] + bv.x),
                                  alpha * (acc[mt][nt][3] + bv.y));
        }
    }
}

// ---------------------------------------------------------------------------
// fused Q + K + V projections; Q segment gathers its A rows via to_sem
__global__ __launch_bounds__(256, 2) void qkv_gemm(
    const float* __restrict__ bq, const float* __restrict__ bk,
    const float* __restrict__ bv, float qscale,
    const void* __restrict__ to_sem)
{
    extern __shared__ char smem[];
    const uint32_t sb = smem_u32(smem);
    const int tid = threadIdx.x;
    const int is64 = g_is64;
    int id = blockIdx.x;

    const __half* W; const float* bias; __half* C;
    float alpha; int bm, bn, gmode;
    if (id < 512) {
        W = g_WQh; bias = bq; C = g_Qh; alpha = qscale; gmode = 1;
        bm = (id >> 3) * 128; bn = (id & 7) * 128;
    } else if (id < 1536) {
        int t = id - 512;
        W = g_WKh; bias = bk; C = g_Kh; alpha = 1.0f; gmode = 0;
        bm = (t >> 3) * 128; bn = (t & 7) * 128;
    } else {
        int t = id - 1536;
        W = g_WVh; bias = bv; C = g_Vh; alpha = 1.0f; gmode = 0;
        bm = (t >> 3) * 128; bn = (t & 7) * 128;
    }

    float acc[2][8][4];
    #pragma unroll
    for (int i = 0; i < 2; i++)
        #pragma unroll
        for (int j = 0; j < 8; j++)
            #pragma unroll
            for (int r = 0; r < 4; r++) acc[i][j][r] = 0.f;

    const __half* Ab = gmode ? g_ENCh : (g_ENCh + (size_t)bm * Dd);
    gemm_tile_core(acc, Ab, Dd, W + (size_t)bn * Dd, Dd, 16, sb, tid,
                   gmode, to_sem, bm, is64);
    epi_half(acc, bias, alpha, C, Dd, bm, bn, tid);
}

// O projection: CTXh @ WOh^T + bo -> CATh (fp16, ldc = KFn)
__global__ __launch_bounds__(256, 2) void o_gemm(const float* __restrict__ bo) {
    extern __shared__ char smem[];
    const uint32_t sb = smem_u32(smem);
    const int tid = threadIdx.x;
    int id = blockIdx.x;
    int bm = (id >> 3) * 128, bn = (id & 7) * 128;

    float acc[2][8][4];
    #pragma unroll
    for (int i = 0; i < 2; i++)
        #pragma unroll
        for (int j = 0; j < 8; j++)
            #pragma unroll
            for (int r = 0; r < 4; r++) acc[i][j][r] = 0.f;

    gemm_tile_core(acc, g_CTXh + (size_t)bm * Dd, Dd, g_WOh + (size_t)bn * Dd, Dd,
                   16, sb, tid, 0, nullptr, 0, 0);
    epi_half(acc, bo, 1.0f, g_CATh, KFn, bm, bn, tid);
}

// final projection: CATh @ WPh^T + b_proj; direct dual store to d_out or fp32 EMB
__global__ __launch_bounds__(256, 2) void p_gemm(const float* __restrict__ bp,
                                                 float* __restrict__ out, int direct) {
    extern __shared__ char smem[];
    const uint32_t sb = smem_u32(smem);
    const int tid = threadIdx.x;
    int id = blockIdx.x;
    int bm = (id >> 3) * 128, bn = (id & 7) * 128;

    float acc[2][8][4];
    #pragma unroll
    for (int i = 0; i < 2; i++)
        #pragma unroll
        for (int j = 0; j < 8; j++)
            #pragma unroll
            for (int r = 0; r < 4; r++) acc[i][j][r] = 0.f;

    gemm_tile_core(acc, g_CATh + (size_t)bm * KFn, KFn, g_WPh + (size_t)bn * KFn, KFn,
                   20, sb, tid, 0, nullptr, 0, 0);

    const int warp = tid >> 5, lane = tid & 31;
    const int wm = warp & 3, wn = warp >> 2;
    const int g = lane >> 2, t2 = (lane & 3) * 2;
    #pragma unroll
    for (int nt = 0; nt < 8; nt++) {
        int c0 = bn + wn * 64 + nt * 8 + t2;
        float2 bv = *(const float2*)(bp + c0);
        #pragma unroll
        for (int mt = 0; mt < 2; mt++) {
            int r0 = bm + wm * 32 + mt * 16 + g;
            float2 o0 = {acc[mt][nt][0] + bv.x, acc[mt][nt][1] + bv.y};
            float2 o1 = {acc[mt][nt][2] + bv.x, acc[mt][nt][3] + bv.y};
            if (direct) {
                int b0 = r0 >> 9, l0 = r0 & 511;
                int rb = r0 + 8;
                int b1 = rb >> 9, l1 = rb & 511;
                *(float2*)(out + (size_t)r0 * Dd + c0) = o0;
                *(float2*)(out + (size_t)rb * Dd + c0) = o1;
                *(float2*)(out + T1c + ((size_t)b0 * (Ls+1) + l0 + 1) * Dd + c0) = o0;
                *(float2*)(out + T1c + ((size_t)b1 * (Ls+1) + l1 + 1) * Dd + c0) = o1;
            } else {
                *(float2*)(g_EMB + (size_t)r0 * Dd + c0)       = o0;
                *(float2*)(g_EMB + (size_t)(r0 + 8) * Dd + c0) = o1;
            }
        }
    }
}

// ---------------------------------------------------------------------------
// fp32 -> fp16 conversion of all 6 tensors + index-dtype detection (seg 6)
__global__ void f2h_all(const float* __restrict__ e, const float* __restrict__ q,
                        const float* __restrict__ k, const float* __restrict__ v,
                        const float* __restrict__ o, const float* __restrict__ p,
                        const void* __restrict__ to_sem) {
    int seg = blockIdx.y;
    if (seg == 6) {
        __shared__ int nz;
        if (threadIdx.x == 0) nz = 0;
        __syncthreads();
        if (blockIdx.x == 0) {
            const int* qw = (const int*)to_sem;
            int bad = 0;
            for (int i = threadIdx.x * 2 + 1; i < 8192; i += 2 * blockDim.x)
                if (qw[i] != 0) bad = 1;
            if (bad) atomicAdd(&nz, 1);
            __syncthreads();
            if (threadIdx.x == 0) g_is64 = (nz == 0) ? 1 : 0;
        }
        return;
    }
    const float* srcs[6] = {e, q, k, v, o, p};
    __half* dsts[6] = {g_ENCh, g_WQh, g_WKh, g_WVh, g_WOh, g_WPh};
    const int n8s[6] = {BSn*Dd/8, Dd*Dd/8, Dd*Dd/8, Dd*Dd/8, Dd*Dd/8, Dd*KFn/8};
    const float* src = srcs[seg];
    __half* dst = dsts[seg];
    int n8 = n8s[seg];
    for (int i = blockIdx.x * blockDim.x + threadIdx.x; i < n8;
         i += gridDim.x * blockDim.x) {
        float4 a = ((const float4*)src)[2*i];
        float4 b = ((const float4*)src)[2*i+1];
        __half2 h[4];
        h[0] = __floats2half2_rn(a.x, a.y);
        h[1] = __floats2half2_rn(a.z, a.w);
        h[2] = __floats2half2_rn(b.x, b.y);
        h[3] = __floats2half2_rn(b.z, b.w);
        ((float4*)dst)[i] = *(float4*)h;
    }
}

// ---------------------------------------------------------------------------
// bucket build: one block per batch; scatter j into per-(b,i) slots.
// (Slot order is nondeterministic; attn sorts, restoring determinism.)
__global__ __launch_bounds__(1024) void build_buckets(const void* __restrict__ sem_syn) {
    int b = blockIdx.x;
    int j = threadIdx.x;
    const int is64 = g_is64;
    if (j < Ls) g_bcnt[b * Ls + j] = 0;
    __syncthreads();
    long long v = is64 ? ((const long long*)sem_syn)[b * Ss + j]
                       : (long long)((const int*)sem_syn)[b * Ss + j];
    if (v >= 1 && v <= Ls) {
        int i = (int)v - 1;
        int slot = atomicAdd(&g_bcnt[b * Ls + i], 1);
        if (slot < BKT) g_bkt[(b * Ls + i) * BKT + slot] = (unsigned short)j;
    }
}

// type embedding into CAT tail; blocks >= 2048 write the root rows of d_out
__global__ void gather_type(const float* __restrict__ temb, const void* __restrict__ tt,
                            const float* __restrict__ root, float* __restrict__ out,
                            int direct) {
    if (blockIdx.x >= 2048) {
        if (direct) {
            int b = blockIdx.x - 2048;
            ((float4*)(out + (size_t)T1c + (size_t)b * (Ls + 1) * Dd))[threadIdx.x] =
                ((const float4*)root)[threadIdx.x];
        }
        return;
    }
    int m = blockIdx.x * 4 + (threadIdx.x >> 6);
    int l = threadIdx.x & 63;
    int t = load_idx_i(tt, m, g_is64);
    float4 v = ((const float4*)(temb + (size_t)t * WDd))[l];
    __half2 h0 = __floats2half2_rn(v.x, v.y);
    __half2 h1 = __floats2half2_rn(v.z, v.w);
    uint2 u = { *(uint32_t*)&h0, *(uint32_t*)&h1 };
    ((uint2*)(g_CATh + (size_t)m * KFn + Dd))[l] = u;
}

// ---------------------------------------------------------------------------
// Sparse masked attention using precomputed buckets; ~3KB smem.
__global__ __launch_bounds__(128) void attn_kernel(
    const void* __restrict__ to_sem, const void* __restrict__ sem_syn)
{
    int bl = blockIdx.x;
    int b = bl >> 9, i = bl & 511;
    int tid = threadIdx.x;

    __shared__ int   s_idx[BKT + 8];
    __shared__ float s_sc[Hh][BKT + 8];
    __shared__ int   s_total;

    const int is64 = g_is64;
    const int base = b * Ss;
    const long long target = (long long)(i + 1);

    int cnt = g_bcnt[bl];
    if (cnt > BKT) cnt = BKT;
    if (tid < cnt) s_idx[tid] = g_bkt[bl * BKT + tid];
    __syncthreads();

    if (tid == 0) {
        // insertion sort ascending (restores deterministic order)
        for (int x = 1; x < cnt; x++) {
            int key = s_idx[x];
            int y = x - 1;
            while (y >= 0 && s_idx[y] > key) { s_idx[y + 1] = s_idx[y]; y--; }
            s_idx[y + 1] = key;
        }
        // append self position if not aligned to this query
        int jself = load_idx_i(to_sem, bl, is64);
        long long vs = is64 ? ((const long long*)sem_syn)[base + jself]
                            : (long long)((const int*)sem_syn)[base + jself];
        int M = cnt;
        if (vs != target) { s_idx[M] = jself; M++; }
        s_total = M;
    }
    __syncthreads();
    const int M = s_total;

    int h = tid >> 4, l16 = tid & 15;
    float qr[8];
    {
        uint4 u = *(const uint4*)(g_Qh + (size_t)bl * Dd + h * DHd + l16 * 8);
        const __half2* hp = (const __half2*)&u;
        float2 f0 = __half22float2(hp[0]), f1 = __half22float2(hp[1]);
        float2 f2 = __half22float2(hp[2]), f3 = __half22float2(hp[3]);
        qr[0]=f0.x; qr[1]=f0.y; qr[2]=f1.x; qr[3]=f1.y;
        qr[4]=f2.x; qr[5]=f2.y; qr[6]=f3.x; qr[7]=f3.y;
    }

    for (int m = 0; m < M; m++) {
        int j = s_idx[m];
        uint4 u = *(const uint4*)(g_Kh + (size_t)(base + j) * Dd + h * DHd + l16 * 8);
        const __half2* hp = (const __half2*)&u;
        float2 k0 = __half22float2(hp[0]), k1 = __half22float2(hp[1]);
        float2 k2 = __half22float2(hp[2]), k3 = __half22float2(hp[3]);
        float p = qr[0]*k0.x + qr[1]*k0.y + qr[2]*k1.x + qr[3]*k1.y
                + qr[4]*k2.x + qr[5]*k2.y + qr[6]*k3.x + qr[7]*k3.y;
        p += __shfl_xor_sync(0xffffffffu, p, 1);
        p += __shfl_xor_sync(0xffffffffu, p, 2);
        p += __shfl_xor_sync(0xffffffffu, p, 4);
        p += __shfl_xor_sync(0xffffffffu, p, 8);
        if (l16 == 0) s_sc[h][m] = p;
    }
    __syncthreads();

    float mx = -3.0e38f;
    for (int m = 0; m < M; m++) mx = fmaxf(mx, s_sc[h][m]);
    float den = 0.f;
    for (int m = 0; m < M; m++) den += expf(s_sc[h][m] - mx);

    float acc[8];
    #pragma unroll
    for (int c = 0; c < 8; c++) acc[c] = 0.f;
    for (int m = 0; m < M; m++) {
        float p = expf(s_sc[h][m] - mx);
        int j = s_idx[m];
        uint4 u = *(const uint4*)(g_Vh + (size_t)(base + j) * Dd + h * DHd + l16 * 8);
        const __half2* hp = (const __half2*)&u;
        float2 v0 = __half22float2(hp[0]), v1 = __half22float2(hp[1]);
        float2 v2 = __half22float2(hp[2]), v3 = __half22float2(hp[3]);
        acc[0] += p * v0.x; acc[1] += p * v0.y; acc[2] += p * v1.x; acc[3] += p * v1.y;
        acc[4] += p * v2.x; acc[5] += p * v2.y; acc[6] += p * v3.x; acc[7] += p * v3.y;
    }
    float inv = 1.0f / den;
    __half2 h0 = __floats2half2_rn(acc[0]*inv, acc[1]*inv);
    __half2 h1 = __floats2half2_rn(acc[2]*inv, acc[3]*inv);
    __half2 h2 = __floats2half2_rn(acc[4]*inv, acc[5]*inv);
    __half2 h3 = __floats2half2_rn(acc[6]*inv, acc[7]*inv);
    uint4 u = { *(uint32_t*)&h0, *(uint32_t*)&h1, *(uint32_t*)&h2, *(uint32_t*)&h3 };
    *(uint4*)(g_CTXh + (size_t)bl * Dd + h * DHd + l16 * 8) = u;
}

// ---------------------------------------------------------------------------
// fallback output packer (only used when out_size doesn't match full tuple)
__global__ void write_out(const float* __restrict__ root, float* __restrict__ out,
                          int out_size) {
    const int T1 = T1c, T2 = T2c;
    int base2, n;
    if (out_size >= T1 + T2)      { base2 = T1; n = T1 + T2; }
    else if (out_size == T2)      { base2 = 0;  n = T2; }
    else                          { base2 = -1; n = T1; }
    int n4 = n >> 2;
    for (int i4 = blockIdx.x * blockDim.x + threadIdx.x; i4 < n4;
         i4 += gridDim.x * blockDim.x) {
        int e = i4 << 2;
        float4 val;
        if (base2 >= 0 && e >= base2) {
            int off = e - base2;
            int b = off / ((Ls + 1) * Dd);
            int r = off - b * ((Ls + 1) * Dd);
            int l = r >> 10;
            int dd = r & (Dd - 1);
            if (l == 0)
                val = ((const float4*)root)[dd >> 2];
            else
                val = ((const float4*)(g_EMB + ((size_t)(b * Ls + l - 1) << 10)))[dd >> 2];
        } else {
            val = ((const float4*)g_EMB)[i4];
        }
        ((float4*)out)[i4] = val;
    }
}

// ---------------------------------------------------------------------------
extern "C" void kernel_launch(void* const* d_in, const int* in_sizes, int n_in,
                              void* d_out, int out_size) {
    const float* enc     = (const float*)d_in[0];
    const void*  to_sem  = d_in[1];
    const void*  tt      = d_in[2];
    const void*  sem_syn = d_in[3];
    const float* bq = (const float*)d_in[5];
    const float* bk = (const float*)d_in[7];
    const float* bv = (const float*)d_in[9];
    const float* bo = (const float*)d_in[11];
    const float* type_emb = (const float*)d_in[12];
    const float* b_proj   = (const float*)d_in[14];
    const float* root     = (const float*)d_in[15];

    cudaFuncSetAttribute(qkv_gemm, cudaFuncAttributeMaxDynamicSharedMemorySize, SM_TOT);
    cudaFuncSetAttribute(o_gemm,   cudaFuncAttributeMaxDynamicSharedMemorySize, SM_TOT);
    cudaFuncSetAttribute(p_gemm,   cudaFuncAttributeMaxDynamicSharedMemorySize, SM_TOT);

    const float qscale = 0.08838834764831843f;   // 1/sqrt(128)
    const int direct = (out_size >= T1c + T2c);

    // conversions + index-dtype detection in one launch
    f2h_all<<<dim3(256, 7), 256>>>(enc, (const float*)d_in[4], (const float*)d_in[6],
                                   (const float*)d_in[8], (const float*)d_in[10],
                                   (const float*)d_in[13], to_sem);
    build_buckets<<<Bz, 1024>>>(sem_syn);
    gather_type<<<2048 + Bz, 256>>>(type_emb, tt, root, (float*)d_out, direct);

    qkv_gemm<<<2560, 256, SM_TOT>>>(bq, bk, bv, qscale, to_sem);

    attn_kernel<<<BLn, 128>>>(to_sem, sem_syn);

    o_gemm<<<512, 256, SM_TOT>>>(bo);

    p_gemm<<<512, 256, SM_TOT>>>(b_proj, (float*)d_out, direct);

    if (!direct) write_out<<<2048, 256>>>(root, (float*)d_out, out_size);
}